// round 1
// baseline (speedup 1.0000x reference)
#include <cuda_runtime.h>

#define IMG 28
#define IMG2 (IMG * IMG)        // 784
#define NVEC (IMG2 / 4)         // 196 float4 per image
#define THREADS 224             // 7 warps; lanes 196..223 idle after load

__global__ __launch_bounds__(THREADS)
void sr_annulus_kernel(const float* __restrict__ x,
                       const int*   __restrict__ t,
                       const float* __restrict__ Wk,
                       const float* __restrict__ bias,
                       float* __restrict__ out)
{
    __shared__ float sx[IMG2];
    __shared__ float sw[9];
    __shared__ float sb;

    const int img = blockIdx.x;
    const int tid = threadIdx.x;

    // Coalesced float4 load of the whole 28x28 image into smem.
    if (tid < NVEC) {
        reinterpret_cast<float4*>(sx)[tid] =
            reinterpret_cast<const float4*>(x + (size_t)img * IMG2)[tid];
    }
    if (tid < 9)  sw[tid] = Wk[tid];
    if (tid == 9) sb = bias[0];

    const int tv = t[img];            // broadcast load
    __syncthreads();

    if (tid >= NVEC) return;

    // Annulus bounds: pixels with lo < dist2 <= hi get x0 added.
    // t=0: lo=-1, hi=0 -> center pixel only (matches r=-1 drawing nothing).
    const int hi = tv * tv;
    const int lo = (tv >= 1) ? (tv - 1) * (tv - 1) : -1;

    const int row  = tid / 7;         // 0..27
    const int col0 = (tid % 7) * 4;   // 0,4,...,24

    float4 v = reinterpret_cast<const float4*>(sx)[tid];
    float res[4] = {v.x, v.y, v.z, v.w};

    const int dr  = row - 14;
    const int dr2 = dr * dr;

    #pragma unroll
    for (int k = 0; k < 4; ++k) {
        const int col = col0 + k;
        const int dc  = col - 14;
        const int d2  = dr2 + dc * dc;
        if (d2 <= hi && d2 > lo) {
            // 3x3 cross-correlation, SAME (zero) padding, + bias
            float acc = sb;
            #pragma unroll
            for (int ki = 0; ki < 3; ++ki) {
                const int r = row + ki - 1;
                if (r < 0 || r >= IMG) continue;
                #pragma unroll
                for (int kj = 0; kj < 3; ++kj) {
                    const int c = col + kj - 1;
                    if (c < 0 || c >= IMG) continue;
                    acc += sx[r * IMG + c] * sw[ki * 3 + kj];
                }
            }
            res[k] += acc;
        }
    }

    reinterpret_cast<float4*>(out + (size_t)img * IMG2)[tid] =
        make_float4(res[0], res[1], res[2], res[3]);
}

extern "C" void kernel_launch(void* const* d_in, const int* in_sizes, int n_in,
                              void* d_out, int out_size)
{
    const float* x    = (const float*)d_in[0];   // [B,1,28,28] f32
    const int*   t    = (const int*)  d_in[1];   // [B] i32
    const float* Wk   = (const float*)d_in[2];   // [1,1,3,3] f32
    const float* bias = (const float*)d_in[3];   // [1] f32
    float* out = (float*)d_out;

    const int B = in_sizes[1];                   // t has B elements
    sr_annulus_kernel<<<B, THREADS>>>(x, t, Wk, bias, out);
}